// round 5
// baseline (speedup 1.0000x reference)
#include <cuda_runtime.h>
#include <cuda_bf16.h>
#include <stdint.h>

#define NNODE 1000000
#define NEDGE 8000000

// Scratch in __device__ globals (no allocation allowed).
__device__ float  g_deg [NNODE];   // in-degree at dst (excl. self-loop)
__device__ float  g_dinv[NNODE];   // rsqrt(deg + 1)
__device__ float4 g_xs  [NNODE];   // x * dinv
__device__ float4 g_acc1[NNODE];   // layer-1 aggregation accumulator
__device__ float2 g_gs  [NNODE];   // (relu(A1 x W1 + b1) W2) * dinv
__device__ float2 g_acc2[NNODE];   // layer-2 aggregation accumulator

// ---------------------------------------------------------------------------
// helpers
__device__ __forceinline__ void red_v4(float4* p, float4 v) {
    asm volatile("red.global.add.v4.f32 [%0], {%1,%2,%3,%4};"
                 :: "l"(p), "f"(v.x), "f"(v.y), "f"(v.z), "f"(v.w) : "memory");
}
__device__ __forceinline__ void red_v2(float2* p, float2 v) {
    asm volatile("red.global.add.v2.f32 [%0], {%1,%2};"
                 :: "l"(p), "f"(v.x), "f"(v.y) : "memory");
}

// ---------------------------------------------------------------------------
// 1. zero the degree array only (acc1/acc2 zeroed inside streaming kernels)
__global__ void k_zero(int n) {
    int i = blockIdx.x * blockDim.x + threadIdx.x;
    if (i < n) g_deg[i] = 0.0f;
}

// ---------------------------------------------------------------------------
// 2. in-degree at dst — 8 edges/thread
__global__ void k_deg(const int* __restrict__ dst, int e) {
    int base = (blockIdx.x * blockDim.x + threadIdx.x) * 8;
    if (base + 8 <= e) {
        int4 d0 = *(const int4*)(dst + base);
        int4 d1 = *(const int4*)(dst + base + 4);
        atomicAdd(&g_deg[d0.x], 1.0f);
        atomicAdd(&g_deg[d0.y], 1.0f);
        atomicAdd(&g_deg[d0.z], 1.0f);
        atomicAdd(&g_deg[d0.w], 1.0f);
        atomicAdd(&g_deg[d1.x], 1.0f);
        atomicAdd(&g_deg[d1.y], 1.0f);
        atomicAdd(&g_deg[d1.z], 1.0f);
        atomicAdd(&g_deg[d1.w], 1.0f);
    } else {
        for (int i = base; i < e; i++) atomicAdd(&g_deg[dst[i]], 1.0f);
    }
}

// ---------------------------------------------------------------------------
// 3. dinv + pre-scaled features; also zeros acc1 (streams along)
__global__ void k_prep(const float4* __restrict__ x, int n) {
    int i = blockIdx.x * blockDim.x + threadIdx.x;
    if (i < n) {
        float di = rsqrtf(g_deg[i] + 1.0f);   // self-loop -> deg >= 1
        g_dinv[i] = di;
        float4 v = x[i];
        v.x *= di; v.y *= di; v.z *= di; v.w *= di;
        g_xs[i]   = v;
        g_acc1[i] = make_float4(0.f, 0.f, 0.f, 0.f);
    }
}

// ---------------------------------------------------------------------------
// 4. layer-1 scatter: acc1[dst] += xs[src] — 8 edges/thread, batched gathers
__global__ void k_scatter1(const int* __restrict__ src,
                           const int* __restrict__ dst, int e) {
    int base = (blockIdx.x * blockDim.x + threadIdx.x) * 8;
    if (base + 8 <= e) {
        int4 s0 = *(const int4*)(src + base);
        int4 s1 = *(const int4*)(src + base + 4);
        int4 d0 = *(const int4*)(dst + base);
        int4 d1 = *(const int4*)(dst + base + 4);
        float4 v0 = g_xs[s0.x];
        float4 v1 = g_xs[s0.y];
        float4 v2 = g_xs[s0.z];
        float4 v3 = g_xs[s0.w];
        float4 v4 = g_xs[s1.x];
        float4 v5 = g_xs[s1.y];
        float4 v6 = g_xs[s1.z];
        float4 v7 = g_xs[s1.w];
        red_v4(&g_acc1[d0.x], v0);
        red_v4(&g_acc1[d0.y], v1);
        red_v4(&g_acc1[d0.z], v2);
        red_v4(&g_acc1[d0.w], v3);
        red_v4(&g_acc1[d1.x], v4);
        red_v4(&g_acc1[d1.y], v5);
        red_v4(&g_acc1[d1.z], v6);
        red_v4(&g_acc1[d1.w], v7);
    } else {
        for (int i = base; i < e; i++)
            red_v4(&g_acc1[dst[i]], g_xs[src[i]]);
    }
}

// ---------------------------------------------------------------------------
// 5. fused node transform; also zeros acc2 (streams along)
__global__ void k_mid(const float* __restrict__ W1,   // [4,64] row-major
                      const float* __restrict__ b1,   // [64]
                      const float* __restrict__ W2,   // [64,2] row-major
                      int n) {
    __shared__ float sW1[256];
    __shared__ float sb1[64];
    __shared__ float sW2[128];
    int t = threadIdx.x;
    if (t < 256) sW1[t] = W1[t];
    if (t < 64)  sb1[t] = b1[t];
    if (t < 128) sW2[t] = W2[t];
    __syncthreads();

    int i = blockIdx.x * blockDim.x + t;
    if (i >= n) return;

    float di = g_dinv[i];
    float4 a  = g_acc1[i];
    float4 xs = g_xs[i];
    float a0 = di * (a.x + xs.x);
    float a1 = di * (a.y + xs.y);
    float a2 = di * (a.z + xs.z);
    float a3 = di * (a.w + xs.w);

    float o0 = 0.f, o1 = 0.f;
#pragma unroll
    for (int j = 0; j < 64; j++) {
        float h = sb1[j];
        h = fmaf(a0, sW1[j],       h);
        h = fmaf(a1, sW1[64 + j],  h);
        h = fmaf(a2, sW1[128 + j], h);
        h = fmaf(a3, sW1[192 + j], h);
        h = fmaxf(h, 0.f);
        o0 = fmaf(h, sW2[2 * j],     o0);
        o1 = fmaf(h, sW2[2 * j + 1], o1);
    }
    g_gs[i]   = make_float2(o0 * di, o1 * di);
    g_acc2[i] = make_float2(0.f, 0.f);
}

// ---------------------------------------------------------------------------
// 6. layer-2 scatter: acc2[dst] += gs[src] — 8 edges/thread
__global__ void k_scatter2(const int* __restrict__ src,
                           const int* __restrict__ dst, int e) {
    int base = (blockIdx.x * blockDim.x + threadIdx.x) * 8;
    if (base + 8 <= e) {
        int4 s0 = *(const int4*)(src + base);
        int4 s1 = *(const int4*)(src + base + 4);
        int4 d0 = *(const int4*)(dst + base);
        int4 d1 = *(const int4*)(dst + base + 4);
        float2 v0 = g_gs[s0.x];
        float2 v1 = g_gs[s0.y];
        float2 v2 = g_gs[s0.z];
        float2 v3 = g_gs[s0.w];
        float2 v4 = g_gs[s1.x];
        float2 v5 = g_gs[s1.y];
        float2 v6 = g_gs[s1.z];
        float2 v7 = g_gs[s1.w];
        red_v2(&g_acc2[d0.x], v0);
        red_v2(&g_acc2[d0.y], v1);
        red_v2(&g_acc2[d0.z], v2);
        red_v2(&g_acc2[d0.w], v3);
        red_v2(&g_acc2[d1.x], v4);
        red_v2(&g_acc2[d1.y], v5);
        red_v2(&g_acc2[d1.z], v6);
        red_v2(&g_acc2[d1.w], v7);
    } else {
        for (int i = base; i < e; i++)
            red_v2(&g_acc2[dst[i]], g_gs[src[i]]);
    }
}

// ---------------------------------------------------------------------------
// 7. final: out = dinv * (acc2 + gs) + b2
__global__ void k_final(const float* __restrict__ b2, float2* __restrict__ out, int n) {
    int i = blockIdx.x * blockDim.x + threadIdx.x;
    if (i < n) {
        float di = g_dinv[i];
        float2 a = g_acc2[i];
        float2 g = g_gs[i];
        float bx = __ldg(&b2[0]);
        float by = __ldg(&b2[1]);
        out[i] = make_float2(di * (a.x + g.x) + bx,
                             di * (a.y + g.y) + by);
    }
}

// ---------------------------------------------------------------------------
extern "C" void kernel_launch(void* const* d_in, const int* in_sizes, int n_in,
                              void* d_out, int out_size) {
    const float* x  = (const float*)d_in[0];   // [N,4]
    const int*   ei = (const int*)d_in[1];     // [2,E]  int32
    const float* W1 = (const float*)d_in[2];   // [4,64]
    const float* b1 = (const float*)d_in[3];   // [64]
    const float* W2 = (const float*)d_in[4];   // [64,2]
    const float* b2 = (const float*)d_in[5];   // [2]
    float2*      out = (float2*)d_out;         // [N,2]

    const int n = in_sizes[0] / 4;
    const int e = in_sizes[1] / 2;
    const int* src = ei;
    const int* dst = ei + e;

    const int T = 256;
    const int gn  = (n + T - 1) / T;
    const int ge8 = ((e + 7) / 8 + T - 1) / T;   // 8 edges/thread

    k_zero    <<<gn,  T>>>(n);
    k_deg     <<<ge8, T>>>(dst, e);
    k_prep    <<<gn,  T>>>((const float4*)x, n);
    k_scatter1<<<ge8, T>>>(src, dst, e);
    k_mid     <<<gn,  T>>>(W1, b1, W2, n);
    k_scatter2<<<ge8, T>>>(src, dst, e);
    k_final   <<<gn,  T>>>(b2, out, n);
}

// round 6
// speedup vs baseline: 1.0392x; 1.0392x over previous
#include <cuda_runtime.h>
#include <cuda_bf16.h>
#include <stdint.h>

#define NNODE 1000000
#define NEDGE 8000000

// Scratch in __device__ globals (no allocation allowed).
__device__ float  g_deg [NNODE];   // in-degree at dst (excl. self-loop)
__device__ float  g_dinv[NNODE];   // rsqrt(deg + 1)
__device__ float4 g_xs  [NNODE];   // x * dinv
__device__ float4 g_acc1[NNODE];   // layer-1 aggregation accumulator
__device__ float2 g_gs  [NNODE];   // (relu(A1 x W1 + b1) W2) * dinv
__device__ float2 g_acc2[NNODE];   // layer-2 aggregation accumulator

// ---------------------------------------------------------------------------
// PDL intrinsics
__device__ __forceinline__ void pdl_wait() {
    asm volatile("griddepcontrol.wait;" ::: "memory");
}
__device__ __forceinline__ void pdl_trigger() {
    asm volatile("griddepcontrol.launch_dependents;" ::: "memory");
}

__device__ __forceinline__ void red_v4(float4* p, float4 v) {
    asm volatile("red.global.add.v4.f32 [%0], {%1,%2,%3,%4};"
                 :: "l"(p), "f"(v.x), "f"(v.y), "f"(v.z), "f"(v.w) : "memory");
}
__device__ __forceinline__ void red_v2(float2* p, float2 v) {
    asm volatile("red.global.add.v2.f32 [%0], {%1,%2};"
                 :: "l"(p), "f"(v.x), "f"(v.y) : "memory");
}

// ---------------------------------------------------------------------------
// 1. zero degree (acc1/acc2 zeroed inside streaming kernels)
__global__ void __launch_bounds__(256) k_zero(int n) {
    int i = blockIdx.x * blockDim.x + threadIdx.x;
    if (i < n) g_deg[i] = 0.0f;
    pdl_trigger();
}

// ---------------------------------------------------------------------------
// 2. in-degree at dst — 4 edges/thread
__global__ void __launch_bounds__(256) k_deg(const int* __restrict__ dst, int e) {
    pdl_wait();
    int base = (blockIdx.x * blockDim.x + threadIdx.x) * 4;
    if (base + 4 <= e) {
        int4 d = *(const int4*)(dst + base);
        atomicAdd(&g_deg[d.x], 1.0f);
        atomicAdd(&g_deg[d.y], 1.0f);
        atomicAdd(&g_deg[d.z], 1.0f);
        atomicAdd(&g_deg[d.w], 1.0f);
    } else {
        for (int i = base; i < e; i++) atomicAdd(&g_deg[dst[i]], 1.0f);
    }
    pdl_trigger();
}

// ---------------------------------------------------------------------------
// 3. dinv + pre-scaled features; zeros acc1
__global__ void __launch_bounds__(256) k_prep(const float4* __restrict__ x, int n) {
    pdl_wait();
    int i = blockIdx.x * blockDim.x + threadIdx.x;
    if (i < n) {
        float di = rsqrtf(g_deg[i] + 1.0f);   // self-loop -> deg >= 1
        g_dinv[i] = di;
        float4 v = x[i];
        v.x *= di; v.y *= di; v.z *= di; v.w *= di;
        g_xs[i]   = v;
        g_acc1[i] = make_float4(0.f, 0.f, 0.f, 0.f);
    }
    pdl_trigger();
}

// ---------------------------------------------------------------------------
// 4. layer-1 scatter: acc1[dst] += xs[src] — 4 edges/thread
__global__ void __launch_bounds__(256) k_scatter1(const int* __restrict__ src,
                                                  const int* __restrict__ dst, int e) {
    pdl_wait();
    int base = (blockIdx.x * blockDim.x + threadIdx.x) * 4;
    if (base + 4 <= e) {
        int4 s = *(const int4*)(src + base);
        int4 d = *(const int4*)(dst + base);
        float4 v0 = g_xs[s.x];
        float4 v1 = g_xs[s.y];
        float4 v2 = g_xs[s.z];
        float4 v3 = g_xs[s.w];
        red_v4(&g_acc1[d.x], v0);
        red_v4(&g_acc1[d.y], v1);
        red_v4(&g_acc1[d.z], v2);
        red_v4(&g_acc1[d.w], v3);
    } else {
        for (int i = base; i < e; i++)
            red_v4(&g_acc1[dst[i]], g_xs[src[i]]);
    }
    pdl_trigger();
}

// ---------------------------------------------------------------------------
// 5. fused node transform; zeros acc2
__global__ void __launch_bounds__(256) k_mid(const float* __restrict__ W1,
                                             const float* __restrict__ b1,
                                             const float* __restrict__ W2,
                                             int n) {
    __shared__ float sW1[256];
    __shared__ float sb1[64];
    __shared__ float sW2[128];
    int t = threadIdx.x;
    // weights are read-only inputs, safe to read before pdl_wait (they are
    // untouched by prior kernels)
    if (t < 256) sW1[t] = W1[t];
    if (t < 64)  sb1[t] = b1[t];
    if (t < 128) sW2[t] = W2[t];
    pdl_wait();
    __syncthreads();

    int i = blockIdx.x * blockDim.x + t;
    if (i >= n) return;

    float di = g_dinv[i];
    float4 a  = g_acc1[i];
    float4 xs = g_xs[i];
    float a0 = di * (a.x + xs.x);
    float a1 = di * (a.y + xs.y);
    float a2 = di * (a.z + xs.z);
    float a3 = di * (a.w + xs.w);

    float o0 = 0.f, o1 = 0.f;
#pragma unroll
    for (int j = 0; j < 64; j++) {
        float h = sb1[j];
        h = fmaf(a0, sW1[j],       h);
        h = fmaf(a1, sW1[64 + j],  h);
        h = fmaf(a2, sW1[128 + j], h);
        h = fmaf(a3, sW1[192 + j], h);
        h = fmaxf(h, 0.f);
        o0 = fmaf(h, sW2[2 * j],     o0);
        o1 = fmaf(h, sW2[2 * j + 1], o1);
    }
    g_gs[i]   = make_float2(o0 * di, o1 * di);
    g_acc2[i] = make_float2(0.f, 0.f);
    pdl_trigger();
}

// ---------------------------------------------------------------------------
// 6. layer-2 scatter: acc2[dst] += gs[src] — 4 edges/thread
__global__ void __launch_bounds__(256) k_scatter2(const int* __restrict__ src,
                                                  const int* __restrict__ dst, int e) {
    pdl_wait();
    int base = (blockIdx.x * blockDim.x + threadIdx.x) * 4;
    if (base + 4 <= e) {
        int4 s = *(const int4*)(src + base);
        int4 d = *(const int4*)(dst + base);
        float2 v0 = g_gs[s.x];
        float2 v1 = g_gs[s.y];
        float2 v2 = g_gs[s.z];
        float2 v3 = g_gs[s.w];
        red_v2(&g_acc2[d.x], v0);
        red_v2(&g_acc2[d.y], v1);
        red_v2(&g_acc2[d.z], v2);
        red_v2(&g_acc2[d.w], v3);
    } else {
        for (int i = base; i < e; i++)
            red_v2(&g_acc2[dst[i]], g_gs[src[i]]);
    }
    pdl_trigger();
}

// ---------------------------------------------------------------------------
// 7. final: out = dinv * (acc2 + gs) + b2
__global__ void __launch_bounds__(256) k_final(const float* __restrict__ b2,
                                               float2* __restrict__ out, int n) {
    float bx = __ldg(&b2[0]);
    float by = __ldg(&b2[1]);
    pdl_wait();
    int i = blockIdx.x * blockDim.x + threadIdx.x;
    if (i < n) {
        float di = g_dinv[i];
        float2 a = g_acc2[i];
        float2 g = g_gs[i];
        out[i] = make_float2(di * (a.x + g.x) + bx,
                             di * (a.y + g.y) + by);
    }
}

// ---------------------------------------------------------------------------
// PDL launch helper
template <typename... Args>
static void pdl_launch(void (*kern)(Args...), int grid, int block,
                       Args... args) {
    cudaLaunchConfig_t cfg = {};
    cfg.gridDim  = dim3(grid, 1, 1);
    cfg.blockDim = dim3(block, 1, 1);
    cfg.dynamicSmemBytes = 0;
    cfg.stream = 0;
    cudaLaunchAttribute attr[1];
    attr[0].id = cudaLaunchAttributeProgrammaticStreamSerialization;
    attr[0].val.programmaticStreamSerializationAllowed = 1;
    cfg.attrs = attr;
    cfg.numAttrs = 1;
    cudaLaunchKernelEx(&cfg, kern, args...);
}

extern "C" void kernel_launch(void* const* d_in, const int* in_sizes, int n_in,
                              void* d_out, int out_size) {
    const float* x  = (const float*)d_in[0];   // [N,4]
    const int*   ei = (const int*)d_in[1];     // [2,E]  int32
    const float* W1 = (const float*)d_in[2];   // [4,64]
    const float* b1 = (const float*)d_in[3];   // [64]
    const float* W2 = (const float*)d_in[4];   // [64,2]
    const float* b2 = (const float*)d_in[5];   // [2]
    float2*      out = (float2*)d_out;         // [N,2]

    const int n = in_sizes[0] / 4;
    const int e = in_sizes[1] / 2;
    const int* src = ei;
    const int* dst = ei + e;

    const int T = 256;
    const int gn  = (n + T - 1) / T;
    const int ge4 = ((e + 3) / 4 + T - 1) / T;   // 4 edges/thread

    pdl_launch(k_zero,     gn,  T, n);
    pdl_launch(k_deg,      ge4, T, dst, e);
    pdl_launch(k_prep,     gn,  T, (const float4*)x, n);
    pdl_launch(k_scatter1, ge4, T, src, dst, e);
    pdl_launch(k_mid,      gn,  T, W1, b1, W2, n);
    pdl_launch(k_scatter2, ge4, T, src, dst, e);
    pdl_launch(k_final,    gn,  T, b2, out, n);
}